// round 9
// baseline (speedup 1.0000x reference)
#include <cuda_runtime.h>
#include <cuda_fp16.h>
#include <math.h>
#include <stdint.h>

// ---------------- problem dims ----------------
#define Bsz 4096
#define Hd  2048
#define Kd  2048
#define AP  (4096ull*2048ull)   // activation plane elems
#define WP  (2048ull*2048ull)   // weight plane elems

// ---------------- device scratch ----------------
__device__ float g_Z [(size_t)Bsz*(5*Hd)];  // [B,5H]: i|f|g|o_part|resid
__device__ float g_Z2[(size_t)Bsz*(2*Hd)];  // [B,2H]: c@w_co | tanh(c)@w_c
// fp16 activations [plane][B][K]; plane: 0=x 1=h 2=c_prev 3=c_new 4=tanh(c_new)
__device__ __half g_Act[5ull*AP];
// fp16 weights transposed [widx][N][K]
// widx: 0 wxi 1 whi 2 wci 3 wxf 4 whf 5 wcf 6 wxg 7 whg 8 wxo 9 who 10 wco 11 wc 12 wi
__device__ __half g_Wt[13ull*WP];

// ---------------- unit tables ----------------
// groups: 0=i 1=f 2=g 3=o 4=resid 5=co 6=c ; each unit = (activation, weight)
__constant__ int c_nunit[7] = {3, 3, 2, 2, 1, 1, 1};
__constant__ unsigned char c_unit_a[7][3] = {
    {0,1,2}, {0,1,2}, {0,1,0}, {0,1,0}, {0,0,0}, {3,0,0}, {4,0,0}
};
__constant__ unsigned char c_unit_w[7][3] = {
    {0,1,2}, {3,4,5}, {6,7,0}, {8,9,0}, {12,0,0}, {10,0,0}, {11,0,0}
};

// ---------------- GEMM tiling ----------------
#define BM 128
#define BN 256
#define BKc 32
#define KPAD 40                    // 32 data + 8 pad: conflict-free ldmatrix
#define THREADS 256
#define A_PL (BM*KPAD)             // 5120 elems = 10240 B
#define W_PL (BN*KPAD)             // 10240 elems = 20480 B
#define ST_ELEMS (A_PL + W_PL)     // 15360 elems = 30720 B / stage
#define STAGES 4
#define SMEM_BYTES (STAGES*ST_ELEMS*2)   // 122880 B -> 1 CTA/SM

__device__ __forceinline__ uint32_t smem_u32(const void* p) {
    uint32_t a;
    asm("{ .reg .u64 t; cvta.to.shared.u64 t, %1; cvt.u32.u64 %0, t; }" : "=r"(a) : "l"(p));
    return a;
}
__device__ __forceinline__ void cp_async16(uint32_t sdst, const void* gsrc) {
    asm volatile("cp.async.cg.shared.global [%0], [%1], 16;"
                 :: "r"(sdst), "l"(__cvta_generic_to_global(gsrc)) : "memory");
}
#define CP_COMMIT() asm volatile("cp.async.commit_group;" ::: "memory")
#define CP_WAIT2()  asm volatile("cp.async.wait_group 2;" ::: "memory")

__device__ __forceinline__ void ldsm_x4(uint32_t& r0, uint32_t& r1, uint32_t& r2, uint32_t& r3,
                                        uint32_t addr) {
    asm volatile("ldmatrix.sync.aligned.m8n8.x4.shared.b16 {%0,%1,%2,%3}, [%4];"
                 : "=r"(r0), "=r"(r1), "=r"(r2), "=r"(r3) : "r"(addr));
}
__device__ __forceinline__ void mma16816(float* d, const uint32_t* a, uint32_t b0, uint32_t b1) {
    asm volatile(
        "mma.sync.aligned.m16n8k16.row.col.f32.f16.f16.f32 "
        "{%0,%1,%2,%3}, {%4,%5,%6,%7}, {%8,%9}, {%0,%1,%2,%3};"
        : "+f"(d[0]), "+f"(d[1]), "+f"(d[2]), "+f"(d[3])
        : "r"(a[0]), "r"(a[1]), "r"(a[2]), "r"(a[3]), "r"(b0), "r"(b1));
}

// ---------------- single-pass fp16 GEMM, 64x64 warp tiles ----------------
__global__ void __launch_bounds__(THREADS, 1) gemm_mma(
    int group_base,
    const float* __restrict__ bi, const float* __restrict__ bf_,
    const float* __restrict__ bg, const float* __restrict__ bo)
{
    extern __shared__ __half smem[];
    const uint32_t sb = smem_u32(smem);

    const int tid  = threadIdx.x;
    const int lane = tid & 31;
    const int wid  = tid >> 5;      // 0..7
    const int wm   = wid & 1;       // 0..1 (64-row slice)
    const int wn   = wid >> 1;      // 0..3 (64-col slice)

    const int group = group_base + ((int)blockIdx.y >> 3);
    const int n0    = ((int)blockIdx.y & 7) * BN;
    const int m0    = (int)blockIdx.x * BM;

    const int nunit = c_nunit[group];
    const int nch   = nunit * (Kd / BKc);    // k32 chunks

    // ldmatrix per-lane byte offsets
    const uint32_t a_off = ((uint32_t)(wm*64 + (lane & 15)) * KPAD + ((lane >> 4) << 3)) * 2;
    const uint32_t w_off = ((uint32_t)(wn*64 + (lane & 7) + ((lane >> 4) << 3)) * KPAD
                            + (((lane >> 3) & 1) << 3)) * 2;

    float acc[4][8][4];
    #pragma unroll
    for (int mi = 0; mi < 4; ++mi)
        #pragma unroll
        for (int nj = 0; nj < 8; ++nj)
            #pragma unroll
            for (int r = 0; r < 4; ++r) acc[mi][nj][r] = 0.0f;

    // stage fill: 1536 x 16B data chunks, 6/thread (pad bytes never read)
    // [0,512): A (128 rows x 4); [512,1536): W (256 rows x 4)
    #define ISSUE(tt, buf) do {                                                        \
        const int _t = (tt);                                                           \
        const int _u  = _t >> 6;                                                       \
        const int _kk = (_t & 63) * BKc;                                               \
        const __half* _gA = g_Act + (size_t)c_unit_a[group][_u]*AP;                    \
        const __half* _gW = g_Wt  + (size_t)c_unit_w[group][_u]*WP;                    \
        const uint32_t _sbase = sb + (uint32_t)(buf)*ST_ELEMS*2;                       \
        _Pragma("unroll")                                                              \
        for (int _i = 0; _i < 6; ++_i) {                                               \
            const int _cid = tid + _i*THREADS;                                         \
            if (_cid < 512) {                                                          \
                const int _r = _cid >> 2, _cc = _cid & 3;                              \
                cp_async16(_sbase + (uint32_t)(_r*KPAD + _cc*8)*2,                     \
                           _gA + (size_t)(m0 + _r)*Kd + _kk + _cc*8);                  \
            } else {                                                                   \
                const int _b = _cid - 512;                                             \
                const int _r = _b >> 2, _cc = _b & 3;                                  \
                cp_async16(_sbase + (uint32_t)(A_PL + _r*KPAD + _cc*8)*2,              \
                           _gW + (size_t)(n0 + _r)*Kd + _kk + _cc*8);                  \
            }                                                                          \
        }                                                                              \
    } while (0)

    // prologue: stages 0..2
    ISSUE(0, 0); CP_COMMIT();
    ISSUE(1, 1); CP_COMMIT();
    ISSUE(2, 2); CP_COMMIT();

    for (int t = 0; t < nch; ++t) {
        CP_WAIT2();
        __syncthreads();

        if (t + 3 < nch) ISSUE(t + 3, (t + 3) & 3);
        CP_COMMIT();   // always commit to keep group counts aligned

        const uint32_t st  = sb + (uint32_t)(t & 3)*ST_ELEMS*2;
        const uint32_t stw = st + (uint32_t)A_PL*2;

        // fragment double buffer across the two k16 halves
        uint32_t a[2][4][4], bw[2][4][4];
        #pragma unroll
        for (int mi = 0; mi < 4; ++mi)
            ldsm_x4(a[0][mi][0], a[0][mi][1], a[0][mi][2], a[0][mi][3],
                    st + a_off + (uint32_t)(mi*16*KPAD)*2);
        #pragma unroll
        for (int nt = 0; nt < 4; ++nt)
            ldsm_x4(bw[0][nt][0], bw[0][nt][1], bw[0][nt][2], bw[0][nt][3],
                    stw + w_off + (uint32_t)(nt*16*KPAD)*2);

        #pragma unroll
        for (int ks = 0; ks < 2; ++ks) {
            if (ks == 0) {
                const uint32_t kso = 32;   // 16 halfs
                #pragma unroll
                for (int mi = 0; mi < 4; ++mi)
                    ldsm_x4(a[1][mi][0], a[1][mi][1], a[1][mi][2], a[1][mi][3],
                            st + a_off + (uint32_t)(mi*16*KPAD)*2 + kso);
                #pragma unroll
                for (int nt = 0; nt < 4; ++nt)
                    ldsm_x4(bw[1][nt][0], bw[1][nt][1], bw[1][nt][2], bw[1][nt][3],
                            stw + w_off + (uint32_t)(nt*16*KPAD)*2 + kso);
            }
            #pragma unroll
            for (int mi = 0; mi < 4; ++mi)
                #pragma unroll
                for (int nj = 0; nj < 8; ++nj)
                    mma16816(acc[mi][nj], a[ks][mi],
                             bw[ks][nj >> 1][(nj & 1)*2], bw[ks][nj >> 1][(nj & 1)*2 + 1]);
        }
    }

    // ---- epilogue ----
    float* zout; size_t ldz; int colbase;
    const float* bias = nullptr;
    if (group < 5) {
        zout = g_Z;  ldz = 5*Hd; colbase = group*Hd + n0;
        if      (group == 0) bias = bi;
        else if (group == 1) bias = bf_;
        else if (group == 2) bias = bg;
        else if (group == 3) bias = bo;
    } else {
        zout = g_Z2; ldz = 2*Hd; colbase = (group - 5)*Hd + n0;
    }

    const int gid = lane >> 2;
    const int tig = lane & 3;

    #pragma unroll
    for (int mi = 0; mi < 4; ++mi) {
        const int row = m0 + wm*64 + mi*16 + gid;
        #pragma unroll
        for (int nj = 0; nj < 8; ++nj) {
            const int ncol = wn*64 + nj*8 + tig*2;
            float b0 = 0.f, b1 = 0.f;
            if (bias) { b0 = bias[n0 + ncol]; b1 = bias[n0 + ncol + 1]; }
            float2 v0 = make_float2(acc[mi][nj][0] + b0, acc[mi][nj][1] + b1);
            float2 v1 = make_float2(acc[mi][nj][2] + b0, acc[mi][nj][3] + b1);
            *(float2*)(zout + (size_t)row       * ldz + colbase + ncol) = v0;
            *(float2*)(zout + (size_t)(row + 8) * ldz + colbase + ncol) = v1;
        }
    }
}

// ---------------- conversion kernels ----------------
// x/h/c fp32 -> fp16 planes 0..2
__global__ void __launch_bounds__(256) conv_act3(
    const float* __restrict__ x, const float* __restrict__ h, const float* __restrict__ c)
{
    const int act = blockIdx.y;
    const float* s = (act == 0) ? x : (act == 1) ? h : c;
    const size_t i = ((size_t)blockIdx.x*256 + threadIdx.x) * 4;
    float4 v = *(const float4*)(s + i);
    __half* dst = g_Act + (size_t)act*AP;
    dst[i+0] = __float2half_rn(v.x);
    dst[i+1] = __float2half_rn(v.y);
    dst[i+2] = __float2half_rn(v.z);
    dst[i+3] = __float2half_rn(v.w);
}

struct WPtrs { const float* p[13]; };

// W[K][N] fp32 -> g_Wt[N][K] fp16 (transpose via smem tile)
__global__ void __launch_bounds__(256) conv_w(WPtrs wp)
{
    __shared__ float t[32][33];
    const int widx = blockIdx.z;
    const float* w = wp.p[widx];
    const int tx = threadIdx.x & 31;
    const int ty = threadIdx.x >> 5;
    const int k0 = blockIdx.x * 32;
    const int n0 = blockIdx.y * 32;
    #pragma unroll
    for (int r = 0; r < 4; ++r)
        t[ty + 8*r][tx] = w[(size_t)(k0 + ty + 8*r)*Hd + n0 + tx];
    __syncthreads();
    __half* dst = g_Wt + (size_t)widx*WP;
    #pragma unroll
    for (int r = 0; r < 4; ++r) {
        const float v = t[tx][ty + 8*r];
        dst[(size_t)(n0 + ty + 8*r)*Kd + k0 + tx] = __float2half_rn(v);
    }
}

// ---------------- elementwise kernels ----------------
__global__ void __launch_bounds__(256) cell_kernel(
    const float* __restrict__ c_prev, float* __restrict__ c_out)
{
    const int idx = blockIdx.x * 256 + threadIdx.x;
    const int m = idx >> 11;
    const int j = idx & (Hd - 1);
    const float* zr = g_Z + (size_t)m * (5*Hd);
    const float iv = zr[j];
    const float fv = zr[Hd + j];
    const float gv = zr[2*Hd + j];
    const float cp = c_prev[idx];
    const float si = 1.0f / (1.0f + expf(-iv));
    const float sf = 1.0f / (1.0f + expf(-fv));
    const float cn = sf * cp + si * tanhf(gv);
    c_out[idx] = cn;
    const float tc = tanhf(cn);
    g_Act[3*AP + idx] = __float2half_rn(cn);
    g_Act[4*AP + idx] = __float2half_rn(tc);
}

__global__ void __launch_bounds__(256) out_kernel(float* __restrict__ h_out)
{
    const int idx = blockIdx.x * 256 + threadIdx.x;
    const int m = idx >> 11;
    const int j = idx & (Hd - 1);
    const float* zr  = g_Z  + (size_t)m * (5*Hd);
    const float* z2r = g_Z2 + (size_t)m * (2*Hd);
    const float o = zr[3*Hd + j] + z2r[j];
    const float t = z2r[Hd + j] + zr[4*Hd + j];
    h_out[idx] = tanhf(o) * t;
}

// ---------------- host launcher ----------------
extern "C" void kernel_launch(void* const* d_in, const int* in_sizes, int n_in,
                              void* d_out, int out_size)
{
    const float* x      = (const float*)d_in[0];
    const float* h_prev = (const float*)d_in[1];
    const float* c_prev = (const float*)d_in[2];
    const float* w_xi = (const float*)d_in[3];
    const float* w_hi = (const float*)d_in[4];
    const float* w_ci = (const float*)d_in[5];
    const float* w_xf = (const float*)d_in[6];
    const float* w_hf = (const float*)d_in[7];
    const float* w_cf = (const float*)d_in[8];
    const float* w_xg = (const float*)d_in[9];
    const float* w_hg = (const float*)d_in[10];
    const float* w_xo = (const float*)d_in[11];
    const float* w_ho = (const float*)d_in[12];
    const float* w_co = (const float*)d_in[13];
    const float* w_c  = (const float*)d_in[14];
    const float* w_i  = (const float*)d_in[15];
    const float* b_i  = (const float*)d_in[16];
    const float* b_f  = (const float*)d_in[17];
    const float* b_g  = (const float*)d_in[18];
    const float* b_o  = (const float*)d_in[19];

    float* out   = (float*)d_out;
    float* h_out = out;
    float* c_out = out + (size_t)Bsz * Hd;

    cudaFuncSetAttribute(gemm_mma, cudaFuncAttributeMaxDynamicSharedMemorySize, SMEM_BYTES);

    const int n = Bsz * Hd;

    conv_act3<<<dim3(n/(256*4), 3), 256>>>(x, h_prev, c_prev);

    WPtrs wp = {{w_xi, w_hi, w_ci, w_xf, w_hf, w_cf, w_xg, w_hg, w_xo, w_ho, w_co, w_c, w_i}};
    conv_w<<<dim3(Kd/32, Hd/32, 13), 256>>>(wp);

    // gemm1: groups 0..4; 8 n-tiles per group, 32 m-tiles
    gemm_mma<<<dim3(Bsz/BM, 5*8), THREADS, SMEM_BYTES>>>(0, b_i, b_f, b_g, b_o);

    cell_kernel<<<n/256, 256>>>(c_prev, c_out);

    // gemm2: groups 5..6
    gemm_mma<<<dim3(Bsz/BM, 2*8), THREADS, SMEM_BYTES>>>(5, nullptr, nullptr, nullptr, nullptr);

    out_kernel<<<n/256, 256>>>(h_out);
}

// round 10
// speedup vs baseline: 1.5142x; 1.5142x over previous
#include <cuda_runtime.h>
#include <cuda_fp16.h>
#include <math.h>
#include <stdint.h>

// ---------------- problem dims ----------------
#define Bsz 4096
#define Hd  2048
#define Kd  2048
#define AP  (4096ull*2048ull)   // activation plane elems
#define WP  (2048ull*2048ull)   // weight plane elems

// ---------------- device scratch ----------------
__device__ float g_Z [(size_t)Bsz*(5*Hd)];  // [B,5H]: i|f|g|o_part|resid
__device__ float g_Z2[(size_t)Bsz*(2*Hd)];  // [B,2H]: c@w_co | tanh(c)@w_c
// fp16 activations [plane][B][K]; plane: 0=x 1=h 2=c_prev 3=c_new 4=tanh(c_new)
__device__ __half g_Act[5ull*AP];
// fp16 weights transposed [widx][N][K]
// widx: 0 wxi 1 whi 2 wci 3 wxf 4 whf 5 wcf 6 wxg 7 whg 8 wxo 9 who 10 wco 11 wc 12 wi
__device__ __half g_Wt[13ull*WP];

// ---------------- unit tables ----------------
// groups: 0=i 1=f 2=g 3=o 4=resid 5=co 6=c ; each unit = (activation, weight)
__constant__ int c_nunit[7] = {3, 3, 2, 2, 1, 1, 1};
__constant__ unsigned char c_unit_a[7][3] = {
    {0,1,2}, {0,1,2}, {0,1,0}, {0,1,0}, {0,0,0}, {3,0,0}, {4,0,0}
};
__constant__ unsigned char c_unit_w[7][3] = {
    {0,1,2}, {3,4,5}, {6,7,0}, {8,9,0}, {12,0,0}, {10,0,0}, {11,0,0}
};

// ---------------- GEMM tiling ----------------
#define BM 128
#define BN 128
#define BKc 64                     // k64 chunks; rows are exactly 128 B
#define THREADS 256
#define A_BYTES (128*128)          // 16384 B (128 rows x 128 B)
#define ST_BYTES (2*A_BYTES)       // 32768 B / stage
#define STAGES 3
#define SMEM_BYTES (STAGES*ST_BYTES)   // 98304 B -> 2 CTAs/SM

__device__ __forceinline__ uint32_t smem_u32(const void* p) {
    uint32_t a;
    asm("{ .reg .u64 t; cvta.to.shared.u64 t, %1; cvt.u32.u64 %0, t; }" : "=r"(a) : "l"(p));
    return a;
}
__device__ __forceinline__ void cp_async16(uint32_t sdst, const void* gsrc) {
    asm volatile("cp.async.cg.shared.global [%0], [%1], 16;"
                 :: "r"(sdst), "l"(__cvta_generic_to_global(gsrc)) : "memory");
}
#define CP_COMMIT() asm volatile("cp.async.commit_group;" ::: "memory")
#define CP_WAIT1()  asm volatile("cp.async.wait_group 1;" ::: "memory")

__device__ __forceinline__ void ldsm_x4(uint32_t& r0, uint32_t& r1, uint32_t& r2, uint32_t& r3,
                                        uint32_t addr) {
    asm volatile("ldmatrix.sync.aligned.m8n8.x4.shared.b16 {%0,%1,%2,%3}, [%4];"
                 : "=r"(r0), "=r"(r1), "=r"(r2), "=r"(r3) : "r"(addr));
}
__device__ __forceinline__ void mma16816(float* d, const uint32_t* a, uint32_t b0, uint32_t b1) {
    asm volatile(
        "mma.sync.aligned.m16n8k16.row.col.f32.f16.f16.f32 "
        "{%0,%1,%2,%3}, {%4,%5,%6,%7}, {%8,%9}, {%0,%1,%2,%3};"
        : "+f"(d[0]), "+f"(d[1]), "+f"(d[2]), "+f"(d[3])
        : "r"(a[0]), "r"(a[1]), "r"(a[2]), "r"(a[3]), "r"(b0), "r"(b1));
}

// ---------------- single-pass fp16 GEMM (k64 chunks, XOR swizzle) ----------------
__global__ void __launch_bounds__(THREADS, 2) gemm_mma(
    int group_base,
    const float* __restrict__ bi, const float* __restrict__ bf_,
    const float* __restrict__ bg, const float* __restrict__ bo)
{
    extern __shared__ __half smem[];
    const uint32_t sb = smem_u32(smem);

    const int tid  = threadIdx.x;
    const int lane = tid & 31;
    const int wid  = tid >> 5;      // 0..7
    const int wm   = wid >> 2;      // 0..1  (64-row slice)
    const int wn   = wid & 3;       // 0..3  (32-col slice)

    const int group = group_base + ((int)blockIdx.y >> 4);
    const int n0    = ((int)blockIdx.y & 15) * BN;
    const int m0    = (int)blockIdx.x * BM;

    const int nunit = c_nunit[group];
    const int nch   = nunit * (Kd / BKc);    // k64 chunks (32/unit)

    // per-lane ldsm row bases (bytes) and swizzle key
    const uint32_t s_key = (uint32_t)(lane & 7);                 // row & 7
    const uint32_t a_row = (uint32_t)(wm*64 + (lane & 15)) * 128;
    const uint32_t w_row = (uint32_t)(wn*32 + (lane & 7) + ((lane >> 4) << 3)) * 128;
    const uint32_t a_c0  = (uint32_t)(lane >> 4);                // 0/1
    const uint32_t w_c0  = (uint32_t)((lane >> 3) & 1);          // 0/1

    float acc[4][4][4];
    #pragma unroll
    for (int mi = 0; mi < 4; ++mi)
        #pragma unroll
        for (int nj = 0; nj < 4; ++nj)
            #pragma unroll
            for (int r = 0; r < 4; ++r) acc[mi][nj][r] = 0.0f;

    // stage fill: 2048 x 16B chunks, 8/thread; swizzled column c ^= (r & 7)
    // [0,1024): A (128 rows x 8 chunks); [1024,2048): W
    #define ISSUE(tt, buf) do {                                                        \
        const int _t = (tt);                                                           \
        const int _u  = _t >> 5;                                                       \
        const int _kk = (_t & 31) * BKc;                                               \
        const __half* _gA = g_Act + (size_t)c_unit_a[group][_u]*AP;                    \
        const __half* _gW = g_Wt  + (size_t)c_unit_w[group][_u]*WP;                    \
        const uint32_t _sbase = sb + (uint32_t)(buf)*ST_BYTES;                         \
        _Pragma("unroll")                                                              \
        for (int _i = 0; _i < 8; ++_i) {                                               \
            const int _cid = tid + _i*THREADS;                                         \
            const int _r = (_cid & 1023) >> 3, _c = _cid & 7;                          \
            const uint32_t _sw = (uint32_t)(_c ^ (_r & 7)) << 4;                       \
            if (_cid < 1024) {                                                         \
                cp_async16(_sbase + (uint32_t)(_r*128) + _sw,                          \
                           _gA + (size_t)(m0 + _r)*Kd + _kk + _c*8);                   \
            } else {                                                                   \
                cp_async16(_sbase + (uint32_t)A_BYTES + (uint32_t)(_r*128) + _sw,      \
                           _gW + (size_t)(n0 + _r)*Kd + _kk + _c*8);                   \
            }                                                                          \
        }                                                                              \
    } while (0)

    // prologue: stages 0,1
    ISSUE(0, 0); CP_COMMIT();
    ISSUE(1, 1); CP_COMMIT();

    int buf = 0;
    for (int t = 0; t < nch; ++t) {
        CP_WAIT1();
        __syncthreads();

        if (t + 2 < nch) {
            int nb = buf + 2; if (nb >= 3) nb -= 3;
            ISSUE(t + 2, nb);
        }
        CP_COMMIT();   // always commit to keep group counts aligned

        const uint32_t st  = sb + (uint32_t)buf*ST_BYTES;
        const uint32_t stw = st + (uint32_t)A_BYTES;

        #pragma unroll
        for (int ks = 0; ks < 4; ++ks) {
            uint32_t a[4][4], bw[2][4];
            #pragma unroll
            for (int mi = 0; mi < 4; ++mi) {
                const uint32_t sw = ((a_c0 + 2*ks) ^ s_key) << 4;
                ldsm_x4(a[mi][0], a[mi][1], a[mi][2], a[mi][3],
                        st + a_row + (uint32_t)(mi*16*128) + sw);
            }
            #pragma unroll
            for (int nt = 0; nt < 2; ++nt) {
                const uint32_t sw = ((w_c0 + 2*ks) ^ s_key) << 4;
                ldsm_x4(bw[nt][0], bw[nt][1], bw[nt][2], bw[nt][3],
                        stw + w_row + (uint32_t)(nt*16*128) + sw);
            }
            #pragma unroll
            for (int mi = 0; mi < 4; ++mi)
                #pragma unroll
                for (int nj = 0; nj < 4; ++nj)
                    mma16816(acc[mi][nj], a[mi],
                             bw[nj >> 1][(nj & 1)*2], bw[nj >> 1][(nj & 1)*2 + 1]);
        }
        if (++buf == 3) buf = 0;
    }

    // ---- epilogue ----
    float* zout; size_t ldz; int colbase;
    const float* bias = nullptr;
    if (group < 5) {
        zout = g_Z;  ldz = 5*Hd; colbase = group*Hd + n0;
        if      (group == 0) bias = bi;
        else if (group == 1) bias = bf_;
        else if (group == 2) bias = bg;
        else if (group == 3) bias = bo;
    } else {
        zout = g_Z2; ldz = 2*Hd; colbase = (group - 5)*Hd + n0;
    }

    const int gid = lane >> 2;
    const int tig = lane & 3;

    #pragma unroll
    for (int mi = 0; mi < 4; ++mi) {
        const int row = m0 + wm*64 + mi*16 + gid;
        #pragma unroll
        for (int nj = 0; nj < 4; ++nj) {
            const int ncol = wn*32 + nj*8 + tig*2;
            float b0 = 0.f, b1 = 0.f;
            if (bias) { b0 = bias[n0 + ncol]; b1 = bias[n0 + ncol + 1]; }
            float2 v0 = make_float2(acc[mi][nj][0] + b0, acc[mi][nj][1] + b1);
            float2 v1 = make_float2(acc[mi][nj][2] + b0, acc[mi][nj][3] + b1);
            *(float2*)(zout + (size_t)row       * ldz + colbase + ncol) = v0;
            *(float2*)(zout + (size_t)(row + 8) * ldz + colbase + ncol) = v1;
        }
    }
}

// ---------------- conversion kernels ----------------
// x/h/c fp32 -> fp16 planes 0..2
__global__ void __launch_bounds__(256) conv_act3(
    const float* __restrict__ x, const float* __restrict__ h, const float* __restrict__ c)
{
    const int act = blockIdx.y;
    const float* s = (act == 0) ? x : (act == 1) ? h : c;
    const size_t i = ((size_t)blockIdx.x*256 + threadIdx.x) * 4;
    float4 v = *(const float4*)(s + i);
    __half* dst = g_Act + (size_t)act*AP;
    dst[i+0] = __float2half_rn(v.x);
    dst[i+1] = __float2half_rn(v.y);
    dst[i+2] = __float2half_rn(v.z);
    dst[i+3] = __float2half_rn(v.w);
}

struct WPtrs { const float* p[13]; };

// W[K][N] fp32 -> g_Wt[N][K] fp16; 64x64 tiles, 16B-vector fp16 writes
__global__ void __launch_bounds__(256) conv_w(WPtrs wp)
{
    __shared__ float t[64][65];
    const int widx = blockIdx.z;
    const float* w = wp.p[widx];
    const int k0 = blockIdx.x * 64;
    const int n0 = blockIdx.y * 64;
    const int tid = threadIdx.x;

    // load 64(k) x 64(n) fp32, float4 per access: 1024 float4, 4/thread
    #pragma unroll
    for (int i = 0; i < 4; ++i) {
        const int idx = tid + i*256;
        const int r  = idx >> 4;           // k row 0..63
        const int c4 = idx & 15;           // float4 col
        float4 v = *(const float4*)(w + (size_t)(k0 + r)*Hd + n0 + c4*4);
        t[r][c4*4+0] = v.x; t[r][c4*4+1] = v.y;
        t[r][c4*4+2] = v.z; t[r][c4*4+3] = v.w;
    }
    __syncthreads();

    __half* dst = g_Wt + (size_t)widx*WP;
    // write 64(n) rows x 64(k): 8 halfs (16B) per store; 512 stores, 2/thread
    #pragma unroll
    for (int i = 0; i < 2; ++i) {
        const int idx = tid + i*256;
        const int n  = idx >> 3;           // 0..63
        const int kc = idx & 7;            // 8-half chunk
        uint32_t pk[4];
        #pragma unroll
        for (int j = 0; j < 4; ++j) {
            __half h0 = __float2half_rn(t[kc*8 + 2*j    ][n]);
            __half h1 = __float2half_rn(t[kc*8 + 2*j + 1][n]);
            __half2 hh = __halves2half2(h0, h1);
            pk[j] = *(uint32_t*)&hh;
        }
        *(uint4*)(dst + (size_t)(n0 + n)*Kd + k0 + kc*8) =
            make_uint4(pk[0], pk[1], pk[2], pk[3]);
    }
}

// ---------------- elementwise kernels ----------------
__global__ void __launch_bounds__(256) cell_kernel(
    const float* __restrict__ c_prev, float* __restrict__ c_out)
{
    const int idx = blockIdx.x * 256 + threadIdx.x;
    const int m = idx >> 11;
    const int j = idx & (Hd - 1);
    const float* zr = g_Z + (size_t)m * (5*Hd);
    const float iv = zr[j];
    const float fv = zr[Hd + j];
    const float gv = zr[2*Hd + j];
    const float cp = c_prev[idx];
    const float si = 1.0f / (1.0f + expf(-iv));
    const float sf = 1.0f / (1.0f + expf(-fv));
    const float cn = sf * cp + si * tanhf(gv);
    c_out[idx] = cn;
    const float tc = tanhf(cn);
    g_Act[3*AP + idx] = __float2half_rn(cn);
    g_Act[4*AP + idx] = __float2half_rn(tc);
}

__global__ void __launch_bounds__(256) out_kernel(float* __restrict__ h_out)
{
    const int idx = blockIdx.x * 256 + threadIdx.x;
    const int m = idx >> 11;
    const int j = idx & (Hd - 1);
    const float* zr  = g_Z  + (size_t)m * (5*Hd);
    const float* z2r = g_Z2 + (size_t)m * (2*Hd);
    const float o = zr[3*Hd + j] + z2r[j];
    const float t = z2r[Hd + j] + zr[4*Hd + j];
    h_out[idx] = tanhf(o) * t;
}

// ---------------- host launcher ----------------
extern "C" void kernel_launch(void* const* d_in, const int* in_sizes, int n_in,
                              void* d_out, int out_size)
{
    const float* x      = (const float*)d_in[0];
    const float* h_prev = (const float*)d_in[1];
    const float* c_prev = (const float*)d_in[2];
    const float* w_xi = (const float*)d_in[3];
    const float* w_hi = (const float*)d_in[4];
    const float* w_ci = (const float*)d_in[5];
    const float* w_xf = (const float*)d_in[6];
    const float* w_hf = (const float*)d_in[7];
    const float* w_cf = (const float*)d_in[8];
    const float* w_xg = (const float*)d_in[9];
    const float* w_hg = (const float*)d_in[10];
    const float* w_xo = (const float*)d_in[11];
    const float* w_ho = (const float*)d_in[12];
    const float* w_co = (const float*)d_in[13];
    const float* w_c  = (const float*)d_in[14];
    const float* w_i  = (const float*)d_in[15];
    const float* b_i  = (const float*)d_in[16];
    const float* b_f  = (const float*)d_in[17];
    const float* b_g  = (const float*)d_in[18];
    const float* b_o  = (const float*)d_in[19];

    float* out   = (float*)d_out;
    float* h_out = out;
    float* c_out = out + (size_t)Bsz * Hd;

    cudaFuncSetAttribute(gemm_mma, cudaFuncAttributeMaxDynamicSharedMemorySize, SMEM_BYTES);

    const int n = Bsz * Hd;

    conv_act3<<<dim3(n/(256*4), 3), 256>>>(x, h_prev, c_prev);

    WPtrs wp = {{w_xi, w_hi, w_ci, w_xf, w_hf, w_cf, w_xg, w_hg, w_xo, w_ho, w_co, w_c, w_i}};
    conv_w<<<dim3(Kd/64, Hd/64, 13), 256>>>(wp);

    // gemm1: groups 0..4; 16 n-tiles per group, 32 m-tiles
    gemm_mma<<<dim3(Bsz/BM, 5*16), THREADS, SMEM_BYTES>>>(0, b_i, b_f, b_g, b_o);

    cell_kernel<<<n/256, 256>>>(c_prev, c_out);

    // gemm2: groups 5..6
    gemm_mma<<<dim3(Bsz/BM, 2*16), THREADS, SMEM_BYTES>>>(5, nullptr, nullptr, nullptr, nullptr);

    out_kernel<<<n/256, 256>>>(h_out);
}

// round 11
// speedup vs baseline: 1.5500x; 1.0237x over previous
#include <cuda_runtime.h>
#include <cuda_fp16.h>
#include <math.h>
#include <stdint.h>

// ---------------- problem dims ----------------
#define Bsz 4096
#define Hd  2048
#define Kd  2048
#define AP  (4096ull*2048ull)   // activation plane elems
#define WP  (2048ull*2048ull)   // weight plane elems

// ---------------- device scratch ----------------
__device__ float g_Z [(size_t)Bsz*(5*Hd)];  // [B,5H]: i|f|g|o_part|resid
__device__ float g_Z2[(size_t)Bsz*(2*Hd)];  // [B,2H]: c@w_co | tanh(c)@w_c
// fp16 activations [plane][B][K]; plane: 0=x 1=h 2=c_prev 3=c_new 4=tanh(c_new)
__device__ __half g_Act[5ull*AP];
// fp16 weights transposed [widx][N][K]
// widx: 0 wxi 1 whi 2 wci 3 wxf 4 whf 5 wcf 6 wxg 7 whg 8 wxo 9 who 10 wco 11 wc 12 wi
__device__ __half g_Wt[13ull*WP];

// ---------------- unit tables ----------------
// groups: 0=i 1=f 2=g 3=o 4=resid 5=co 6=c ; each unit = (activation, weight)
__constant__ int c_nunit[7] = {3, 3, 2, 2, 1, 1, 1};
__constant__ unsigned char c_unit_a[7][3] = {
    {0,1,2}, {0,1,2}, {0,1,0}, {0,1,0}, {0,0,0}, {3,0,0}, {4,0,0}
};
__constant__ unsigned char c_unit_w[7][3] = {
    {0,1,2}, {3,4,5}, {6,7,0}, {8,9,0}, {12,0,0}, {10,0,0}, {11,0,0}
};

// ---------------- GEMM tiling ----------------
#define BM 128
#define BN 128
#define BKc 64                     // k64 chunks; rows are exactly 128 B
#define THREADS 256
#define A_BYTES (128*128)          // 16384 B (128 rows x 128 B)
#define ST_BYTES (2*A_BYTES)       // 32768 B / stage
#define STAGES 3
#define SMEM_BYTES (STAGES*ST_BYTES)   // 98304 B -> 2 CTAs/SM

__device__ __forceinline__ uint32_t smem_u32(const void* p) {
    uint32_t a;
    asm("{ .reg .u64 t; cvta.to.shared.u64 t, %1; cvt.u32.u64 %0, t; }" : "=r"(a) : "l"(p));
    return a;
}
__device__ __forceinline__ void cp_async16(uint32_t sdst, const void* gsrc) {
    asm volatile("cp.async.cg.shared.global [%0], [%1], 16;"
                 :: "r"(sdst), "l"(__cvta_generic_to_global(gsrc)) : "memory");
}
#define CP_COMMIT() asm volatile("cp.async.commit_group;" ::: "memory")
#define CP_WAIT1()  asm volatile("cp.async.wait_group 1;" ::: "memory")

__device__ __forceinline__ void ldsm_x4(uint32_t& r0, uint32_t& r1, uint32_t& r2, uint32_t& r3,
                                        uint32_t addr) {
    asm volatile("ldmatrix.sync.aligned.m8n8.x4.shared.b16 {%0,%1,%2,%3}, [%4];"
                 : "=r"(r0), "=r"(r1), "=r"(r2), "=r"(r3) : "r"(addr));
}
__device__ __forceinline__ void mma16816(float* d, const uint32_t* a, uint32_t b0, uint32_t b1) {
    asm volatile(
        "mma.sync.aligned.m16n8k16.row.col.f32.f16.f16.f32 "
        "{%0,%1,%2,%3}, {%4,%5,%6,%7}, {%8,%9}, {%0,%1,%2,%3};"
        : "+f"(d[0]), "+f"(d[1]), "+f"(d[2]), "+f"(d[3])
        : "r"(a[0]), "r"(a[1]), "r"(a[2]), "r"(a[3]), "r"(b0), "r"(b1));
}

// ---------------- single-pass fp16 GEMM (k64 chunks, XOR swizzle, frag pipelining) ----------------
__global__ void __launch_bounds__(THREADS, 2) gemm_mma(
    int group_base,
    const float* __restrict__ bi, const float* __restrict__ bf_,
    const float* __restrict__ bg, const float* __restrict__ bo)
{
    extern __shared__ __half smem[];
    const uint32_t sb = smem_u32(smem);

    const int tid  = threadIdx.x;
    const int lane = tid & 31;
    const int wid  = tid >> 5;      // 0..7
    const int wm   = wid >> 2;      // 0..1  (64-row slice)
    const int wn   = wid & 3;       // 0..3  (32-col slice)

    const int group = group_base + ((int)blockIdx.y >> 4);
    const int n0    = ((int)blockIdx.y & 15) * BN;
    const int m0    = (int)blockIdx.x * BM;

    const int nunit = c_nunit[group];
    const int nch   = nunit * (Kd / BKc);    // k64 chunks (32/unit)

    // per-lane ldsm row bases (bytes) and swizzle key
    const uint32_t s_key = (uint32_t)(lane & 7);                 // row & 7
    const uint32_t a_row = (uint32_t)(wm*64 + (lane & 15)) * 128;
    const uint32_t w_row = (uint32_t)(wn*32 + (lane & 7) + ((lane >> 4) << 3)) * 128;
    const uint32_t a_c0  = (uint32_t)(lane >> 4);                // 0/1
    const uint32_t w_c0  = (uint32_t)((lane >> 3) & 1);          // 0/1

    float acc[4][4][4];
    #pragma unroll
    for (int mi = 0; mi < 4; ++mi)
        #pragma unroll
        for (int nj = 0; nj < 4; ++nj)
            #pragma unroll
            for (int r = 0; r < 4; ++r) acc[mi][nj][r] = 0.0f;

    // stage fill: 2048 x 16B chunks, 8/thread; swizzled column c ^= (r & 7)
    // [0,1024): A (128 rows x 8 chunks); [1024,2048): W
    #define ISSUE(tt, buf) do {                                                        \
        const int _t = (tt);                                                           \
        const int _u  = _t >> 5;                                                       \
        const int _kk = (_t & 31) * BKc;                                               \
        const __half* _gA = g_Act + (size_t)c_unit_a[group][_u]*AP;                    \
        const __half* _gW = g_Wt  + (size_t)c_unit_w[group][_u]*WP;                    \
        const uint32_t _sbase = sb + (uint32_t)(buf)*ST_BYTES;                         \
        _Pragma("unroll")                                                              \
        for (int _i = 0; _i < 8; ++_i) {                                               \
            const int _cid = tid + _i*THREADS;                                         \
            const int _r = (_cid & 1023) >> 3, _c = _cid & 7;                          \
            const uint32_t _sw = (uint32_t)(_c ^ (_r & 7)) << 4;                       \
            if (_cid < 1024) {                                                         \
                cp_async16(_sbase + (uint32_t)(_r*128) + _sw,                          \
                           _gA + (size_t)(m0 + _r)*Kd + _kk + _c*8);                   \
            } else {                                                                   \
                cp_async16(_sbase + (uint32_t)A_BYTES + (uint32_t)(_r*128) + _sw,      \
                           _gW + (size_t)(n0 + _r)*Kd + _kk + _c*8);                   \
            }                                                                          \
        }                                                                              \
    } while (0)

    // fragment load for k16 slice ks into register set (ab, bb)
    #define LOADFRAG(ks_, ab, bb) do {                                                 \
        const uint32_t _swa = ((a_c0 + 2*(ks_)) ^ s_key) << 4;                         \
        const uint32_t _sww = ((w_c0 + 2*(ks_)) ^ s_key) << 4;                         \
        _Pragma("unroll")                                                              \
        for (int _mi = 0; _mi < 4; ++_mi)                                              \
            ldsm_x4((ab)[_mi][0], (ab)[_mi][1], (ab)[_mi][2], (ab)[_mi][3],            \
                    st + a_row + (uint32_t)(_mi*16*128) + _swa);                       \
        _Pragma("unroll")                                                              \
        for (int _nt = 0; _nt < 2; ++_nt)                                              \
            ldsm_x4((bb)[_nt][0], (bb)[_nt][1], (bb)[_nt][2], (bb)[_nt][3],            \
                    stw + w_row + (uint32_t)(_nt*16*128) + _sww);                      \
    } while (0)

    // prologue: stages 0,1
    ISSUE(0, 0); CP_COMMIT();
    ISSUE(1, 1); CP_COMMIT();

    int buf = 0;
    for (int t = 0; t < nch; ++t) {
        CP_WAIT1();
        __syncthreads();

        if (t + 2 < nch) {
            int nb = buf + 2; if (nb >= 3) nb -= 3;
            ISSUE(t + 2, nb);
        }
        CP_COMMIT();   // always commit to keep group counts aligned

        const uint32_t st  = sb + (uint32_t)buf*ST_BYTES;
        const uint32_t stw = st + (uint32_t)A_BYTES;

        uint32_t a[2][4][4], bw[2][2][4];
        LOADFRAG(0, a[0], bw[0]);

        #pragma unroll
        for (int ks = 0; ks < 4; ++ks) {
            const int cur = ks & 1;
            if (ks < 3) LOADFRAG(ks + 1, a[cur ^ 1], bw[cur ^ 1]);
            #pragma unroll
            for (int mi = 0; mi < 4; ++mi)
                #pragma unroll
                for (int nj = 0; nj < 4; ++nj)
                    mma16816(acc[mi][nj], a[cur][mi],
                             bw[cur][nj >> 1][(nj & 1)*2], bw[cur][nj >> 1][(nj & 1)*2 + 1]);
        }
        if (++buf == 3) buf = 0;
    }

    // ---- epilogue ----
    float* zout; size_t ldz; int colbase;
    const float* bias = nullptr;
    if (group < 5) {
        zout = g_Z;  ldz = 5*Hd; colbase = group*Hd + n0;
        if      (group == 0) bias = bi;
        else if (group == 1) bias = bf_;
        else if (group == 2) bias = bg;
        else if (group == 3) bias = bo;
    } else {
        zout = g_Z2; ldz = 2*Hd; colbase = (group - 5)*Hd + n0;
    }

    const int gid = lane >> 2;
    const int tig = lane & 3;

    #pragma unroll
    for (int mi = 0; mi < 4; ++mi) {
        const int row = m0 + wm*64 + mi*16 + gid;
        #pragma unroll
        for (int nj = 0; nj < 4; ++nj) {
            const int ncol = wn*32 + nj*8 + tig*2;
            float b0 = 0.f, b1 = 0.f;
            if (bias) { b0 = bias[n0 + ncol]; b1 = bias[n0 + ncol + 1]; }
            float2 v0 = make_float2(acc[mi][nj][0] + b0, acc[mi][nj][1] + b1);
            float2 v1 = make_float2(acc[mi][nj][2] + b0, acc[mi][nj][3] + b1);
            *(float2*)(zout + (size_t)row       * ldz + colbase + ncol) = v0;
            *(float2*)(zout + (size_t)(row + 8) * ldz + colbase + ncol) = v1;
        }
    }
}

// ---------------- conversion kernels ----------------
// x/h/c fp32 -> fp16 planes 0..2
__global__ void __launch_bounds__(256) conv_act3(
    const float* __restrict__ x, const float* __restrict__ h, const float* __restrict__ c)
{
    const int act = blockIdx.y;
    const float* s = (act == 0) ? x : (act == 1) ? h : c;
    const size_t i = ((size_t)blockIdx.x*256 + threadIdx.x) * 4;
    float4 v = *(const float4*)(s + i);
    __half* dst = g_Act + (size_t)act*AP;
    __half2 h0 = __halves2half2(__float2half_rn(v.x), __float2half_rn(v.y));
    __half2 h1 = __halves2half2(__float2half_rn(v.z), __float2half_rn(v.w));
    *(uint2*)(dst + i) = make_uint2(*(uint32_t*)&h0, *(uint32_t*)&h1);
}

struct WPtrs { const float* p[13]; };

// W[K][N] fp32 -> g_Wt[N][K] fp16; 64x64 tiles, 16B-vector fp16 writes
__global__ void __launch_bounds__(256) conv_w(WPtrs wp)
{
    __shared__ float t[64][65];
    const int widx = blockIdx.z;
    const float* w = wp.p[widx];
    const int k0 = blockIdx.x * 64;
    const int n0 = blockIdx.y * 64;
    const int tid = threadIdx.x;

    #pragma unroll
    for (int i = 0; i < 4; ++i) {
        const int idx = tid + i*256;
        const int r  = idx >> 4;
        const int c4 = idx & 15;
        float4 v = *(const float4*)(w + (size_t)(k0 + r)*Hd + n0 + c4*4);
        t[r][c4*4+0] = v.x; t[r][c4*4+1] = v.y;
        t[r][c4*4+2] = v.z; t[r][c4*4+3] = v.w;
    }
    __syncthreads();

    __half* dst = g_Wt + (size_t)widx*WP;
    #pragma unroll
    for (int i = 0; i < 2; ++i) {
        const int idx = tid + i*256;
        const int n  = idx >> 3;
        const int kc = idx & 7;
        uint32_t pk[4];
        #pragma unroll
        for (int j = 0; j < 4; ++j) {
            __half h0 = __float2half_rn(t[kc*8 + 2*j    ][n]);
            __half h1 = __float2half_rn(t[kc*8 + 2*j + 1][n]);
            __half2 hh = __halves2half2(h0, h1);
            pk[j] = *(uint32_t*)&hh;
        }
        *(uint4*)(dst + (size_t)(n0 + n)*Kd + k0 + kc*8) =
            make_uint4(pk[0], pk[1], pk[2], pk[3]);
    }
}

// ---------------- elementwise kernels (float4 vectorized) ----------------
__global__ void __launch_bounds__(256) cell_kernel(
    const float* __restrict__ c_prev, float* __restrict__ c_out)
{
    const int idx = (blockIdx.x * 256 + threadIdx.x) * 4;   // 4-aligned within a row
    const int m = idx >> 11;
    const int j = idx & (Hd - 1);
    const float* zr = g_Z + (size_t)m * (5*Hd);
    float4 iv = *(const float4*)(zr + j);
    float4 fv = *(const float4*)(zr + Hd + j);
    float4 gv = *(const float4*)(zr + 2*Hd + j);
    float4 cp = *(const float4*)(c_prev + idx);
    float cn[4], tc[4];
    const float* ivp = (const float*)&iv;
    const float* fvp = (const float*)&fv;
    const float* gvp = (const float*)&gv;
    const float* cpp = (const float*)&cp;
    #pragma unroll
    for (int r = 0; r < 4; ++r) {
        const float si = 1.0f / (1.0f + expf(-ivp[r]));
        const float sf = 1.0f / (1.0f + expf(-fvp[r]));
        cn[r] = sf * cpp[r] + si * tanhf(gvp[r]);
        tc[r] = tanhf(cn[r]);
    }
    *(float4*)(c_out + idx) = make_float4(cn[0], cn[1], cn[2], cn[3]);
    __half2 c0 = __halves2half2(__float2half_rn(cn[0]), __float2half_rn(cn[1]));
    __half2 c1 = __halves2half2(__float2half_rn(cn[2]), __float2half_rn(cn[3]));
    __half2 t0 = __halves2half2(__float2half_rn(tc[0]), __float2half_rn(tc[1]));
    __half2 t1 = __halves2half2(__float2half_rn(tc[2]), __float2half_rn(tc[3]));
    *(uint2*)(g_Act + 3*AP + idx) = make_uint2(*(uint32_t*)&c0, *(uint32_t*)&c1);
    *(uint2*)(g_Act + 4*AP + idx) = make_uint2(*(uint32_t*)&t0, *(uint32_t*)&t1);
}

__global__ void __launch_bounds__(256) out_kernel(float* __restrict__ h_out)
{
    const int idx = (blockIdx.x * 256 + threadIdx.x) * 4;
    const int m = idx >> 11;
    const int j = idx & (Hd - 1);
    const float* zr  = g_Z  + (size_t)m * (5*Hd);
    const float* z2r = g_Z2 + (size_t)m * (2*Hd);
    float4 op = *(const float4*)(zr + 3*Hd + j);
    float4 rs = *(const float4*)(zr + 4*Hd + j);
    float4 zc = *(const float4*)(z2r + j);
    float4 zt = *(const float4*)(z2r + Hd + j);
    const float* opp = (const float*)&op;
    const float* rsp = (const float*)&rs;
    const float* zcp = (const float*)&zc;
    const float* ztp = (const float*)&zt;
    float hv[4];
    #pragma unroll
    for (int r = 0; r < 4; ++r)
        hv[r] = tanhf(opp[r] + zcp[r]) * (ztp[r] + rsp[r]);
    *(float4*)(h_out + idx) = make_float4(hv[0], hv[1], hv[2], hv[3]);
}

// ---------------- host launcher ----------------
extern "C" void kernel_launch(void* const* d_in, const int* in_sizes, int n_in,
                              void* d_out, int out_size)
{
    const float* x      = (const float*)d_in[0];
    const float* h_prev = (const float*)d_in[1];
    const float* c_prev = (const float*)d_in[2];
    const float* w_xi = (const float*)d_in[3];
    const float* w_hi = (const float*)d_in[4];
    const float* w_ci = (const float*)d_in[5];
    const float* w_xf = (const float*)d_in[6];
    const float* w_hf = (const float*)d_in[7];
    const float* w_cf = (const float*)d_in[8];
    const float* w_xg = (const float*)d_in[9];
    const float* w_hg = (const float*)d_in[10];
    const float* w_xo = (const float*)d_in[11];
    const float* w_ho = (const float*)d_in[12];
    const float* w_co = (const float*)d_in[13];
    const float* w_c  = (const float*)d_in[14];
    const float* w_i  = (const float*)d_in[15];
    const float* b_i  = (const float*)d_in[16];
    const float* b_f  = (const float*)d_in[17];
    const float* b_g  = (const float*)d_in[18];
    const float* b_o  = (const float*)d_in[19];

    float* out   = (float*)d_out;
    float* h_out = out;
    float* c_out = out + (size_t)Bsz * Hd;

    cudaFuncSetAttribute(gemm_mma, cudaFuncAttributeMaxDynamicSharedMemorySize, SMEM_BYTES);

    const int n = Bsz * Hd;

    conv_act3<<<dim3(n/(256*4), 3), 256>>>(x, h_prev, c_prev);

    WPtrs wp = {{w_xi, w_hi, w_ci, w_xf, w_hf, w_cf, w_xg, w_hg, w_xo, w_ho, w_co, w_c, w_i}};
    conv_w<<<dim3(Kd/64, Hd/64, 13), 256>>>(wp);

    // gemm1: groups 0..4; 16 n-tiles per group, 32 m-tiles
    gemm_mma<<<dim3(Bsz/BM, 5*16), THREADS, SMEM_BYTES>>>(0, b_i, b_f, b_g, b_o);

    cell_kernel<<<n/(256*4), 256>>>(c_prev, c_out);

    // gemm2: groups 5..6
    gemm_mma<<<dim3(Bsz/BM, 2*16), THREADS, SMEM_BYTES>>>(5, nullptr, nullptr, nullptr, nullptr);

    out_kernel<<<n/(256*4), 256>>>(h_out);
}

// round 12
// speedup vs baseline: 1.5520x; 1.0012x over previous
#include <cuda_runtime.h>
#include <cuda_fp16.h>
#include <math.h>
#include <stdint.h>

// ---------------- problem dims ----------------
#define Bsz 4096
#define Hd  2048
#define Kd  2048
#define AP  (4096ull*2048ull)   // activation plane elems
#define WP  (2048ull*2048ull)   // weight plane elems

// ---------------- device scratch ----------------
__device__ float g_Z [(size_t)Bsz*(5*Hd)];  // [B,5H]: i|f|g|o_part|resid
__device__ float g_Z2[(size_t)Bsz*(2*Hd)];  // [B,2H]: c@w_co | tanh(c)@w_c
// fp16 activations [plane][B][K]; plane: 0=x 1=h 2=c_prev 3=c_new 4=tanh(c_new)
__device__ __half g_Act[5ull*AP];
// fp16 weights transposed [widx][N][K]
// widx: 0 wxi 1 whi 2 wci 3 wxf 4 whf 5 wcf 6 wxg 7 whg 8 wxo 9 who 10 wco 11 wc 12 wi
__device__ __half g_Wt[13ull*WP];

// ---------------- unit tables ----------------
// groups: 0=i 1=f 2=g 3=o 4=resid 5=co 6=c ; each unit = (activation, weight)
__constant__ int c_nunit[7] = {3, 3, 2, 2, 1, 1, 1};
__constant__ unsigned char c_unit_a[7][3] = {
    {0,1,2}, {0,1,2}, {0,1,0}, {0,1,0}, {0,0,0}, {3,0,0}, {4,0,0}
};
__constant__ unsigned char c_unit_w[7][3] = {
    {0,1,2}, {3,4,5}, {6,7,0}, {8,9,0}, {12,0,0}, {10,0,0}, {11,0,0}
};
// phase 0: groups {i,f,g} (everything cell needs); phase 1: {o,resid,co,c}
__constant__ signed char c_phase_groups[2][4] = { {0,1,2,-1}, {3,4,5,6} };

// ---------------- GEMM tiling ----------------
#define BM 128
#define BN 128
#define BKc 64                     // k64 chunks; rows are exactly 128 B
#define THREADS 256
#define A_BYTES (128*128)          // 16384 B (128 rows x 128 B)
#define ST_BYTES (2*A_BYTES)       // 32768 B / stage
#define STAGES 3
#define SMEM_BYTES (STAGES*ST_BYTES)   // 98304 B -> 2 CTAs/SM

__device__ __forceinline__ uint32_t smem_u32(const void* p) {
    uint32_t a;
    asm("{ .reg .u64 t; cvta.to.shared.u64 t, %1; cvt.u32.u64 %0, t; }" : "=r"(a) : "l"(p));
    return a;
}
__device__ __forceinline__ void cp_async16(uint32_t sdst, const void* gsrc) {
    asm volatile("cp.async.cg.shared.global [%0], [%1], 16;"
                 :: "r"(sdst), "l"(__cvta_generic_to_global(gsrc)) : "memory");
}
#define CP_COMMIT() asm volatile("cp.async.commit_group;" ::: "memory")
#define CP_WAIT1()  asm volatile("cp.async.wait_group 1;" ::: "memory")

__device__ __forceinline__ void ldsm_x4(uint32_t& r0, uint32_t& r1, uint32_t& r2, uint32_t& r3,
                                        uint32_t addr) {
    asm volatile("ldmatrix.sync.aligned.m8n8.x4.shared.b16 {%0,%1,%2,%3}, [%4];"
                 : "=r"(r0), "=r"(r1), "=r"(r2), "=r"(r3) : "r"(addr));
}
__device__ __forceinline__ void mma16816(float* d, const uint32_t* a, uint32_t b0, uint32_t b1) {
    asm volatile(
        "mma.sync.aligned.m16n8k16.row.col.f32.f16.f16.f32 "
        "{%0,%1,%2,%3}, {%4,%5,%6,%7}, {%8,%9}, {%0,%1,%2,%3};"
        : "+f"(d[0]), "+f"(d[1]), "+f"(d[2]), "+f"(d[3])
        : "r"(a[0]), "r"(a[1]), "r"(a[2]), "r"(a[3]), "r"(b0), "r"(b1));
}

// ---------------- single-pass fp16 GEMM (k64 chunks, XOR swizzle, frag pipelining) ----------------
__global__ void __launch_bounds__(THREADS, 2) gemm_mma(
    int phase,
    const float* __restrict__ bi, const float* __restrict__ bf_,
    const float* __restrict__ bg, const float* __restrict__ bo)
{
    extern __shared__ __half smem[];
    const uint32_t sb = smem_u32(smem);

    const int tid  = threadIdx.x;
    const int lane = tid & 31;
    const int wid  = tid >> 5;      // 0..7
    const int wm   = wid >> 2;      // 0..1  (64-row slice)
    const int wn   = wid & 3;       // 0..3  (32-col slice)

    const int group = c_phase_groups[phase][(int)blockIdx.y >> 4];
    const int n0    = ((int)blockIdx.y & 15) * BN;
    const int m0    = (int)blockIdx.x * BM;

    const int nunit = c_nunit[group];
    const int nch   = nunit * (Kd / BKc);    // k64 chunks (32/unit)

    // per-lane ldsm row bases (bytes) and swizzle key
    const uint32_t s_key = (uint32_t)(lane & 7);                 // row & 7
    const uint32_t a_row = (uint32_t)(wm*64 + (lane & 15)) * 128;
    const uint32_t w_row = (uint32_t)(wn*32 + (lane & 7) + ((lane >> 4) << 3)) * 128;
    const uint32_t a_c0  = (uint32_t)(lane >> 4);                // 0/1
    const uint32_t w_c0  = (uint32_t)((lane >> 3) & 1);          // 0/1

    float acc[4][4][4];
    #pragma unroll
    for (int mi = 0; mi < 4; ++mi)
        #pragma unroll
        for (int nj = 0; nj < 4; ++nj)
            #pragma unroll
            for (int r = 0; r < 4; ++r) acc[mi][nj][r] = 0.0f;

    // stage fill: 2048 x 16B chunks, 8/thread; swizzled column c ^= (r & 7)
    // [0,1024): A (128 rows x 8 chunks); [1024,2048): W
    #define ISSUE(tt, buf) do {                                                        \
        const int _t = (tt);                                                           \
        const int _u  = _t >> 5;                                                       \
        const int _kk = (_t & 31) * BKc;                                               \
        const __half* _gA = g_Act + (size_t)c_unit_a[group][_u]*AP;                    \
        const __half* _gW = g_Wt  + (size_t)c_unit_w[group][_u]*WP;                    \
        const uint32_t _sbase = sb + (uint32_t)(buf)*ST_BYTES;                         \
        _Pragma("unroll")                                                              \
        for (int _i = 0; _i < 8; ++_i) {                                               \
            const int _cid = tid + _i*THREADS;                                         \
            const int _r = (_cid & 1023) >> 3, _c = _cid & 7;                          \
            const uint32_t _sw = (uint32_t)(_c ^ (_r & 7)) << 4;                       \
            if (_cid < 1024) {                                                         \
                cp_async16(_sbase + (uint32_t)(_r*128) + _sw,                          \
                           _gA + (size_t)(m0 + _r)*Kd + _kk + _c*8);                   \
            } else {                                                                   \
                cp_async16(_sbase + (uint32_t)A_BYTES + (uint32_t)(_r*128) + _sw,      \
                           _gW + (size_t)(n0 + _r)*Kd + _kk + _c*8);                   \
            }                                                                          \
        }                                                                              \
    } while (0)

    // fragment load for k16 slice ks into register set (ab, bb)
    #define LOADFRAG(ks_, ab, bb) do {                                                 \
        const uint32_t _swa = ((a_c0 + 2*(ks_)) ^ s_key) << 4;                         \
        const uint32_t _sww = ((w_c0 + 2*(ks_)) ^ s_key) << 4;                         \
        _Pragma("unroll")                                                              \
        for (int _mi = 0; _mi < 4; ++_mi)                                              \
            ldsm_x4((ab)[_mi][0], (ab)[_mi][1], (ab)[_mi][2], (ab)[_mi][3],            \
                    st + a_row + (uint32_t)(_mi*16*128) + _swa);                       \
        _Pragma("unroll")                                                              \
        for (int _nt = 0; _nt < 2; ++_nt)                                              \
            ldsm_x4((bb)[_nt][0], (bb)[_nt][1], (bb)[_nt][2], (bb)[_nt][3],            \
                    stw + w_row + (uint32_t)(_nt*16*128) + _sww);                      \
    } while (0)

    // prologue: stages 0,1
    ISSUE(0, 0); CP_COMMIT();
    ISSUE(1, 1); CP_COMMIT();

    int buf = 0;
    for (int t = 0; t < nch; ++t) {
        CP_WAIT1();
        __syncthreads();

        if (t + 2 < nch) {
            int nb = buf + 2; if (nb >= 3) nb -= 3;
            ISSUE(t + 2, nb);
        }
        CP_COMMIT();   // always commit to keep group counts aligned

        const uint32_t st  = sb + (uint32_t)buf*ST_BYTES;
        const uint32_t stw = st + (uint32_t)A_BYTES;

        uint32_t a[2][4][4], bw[2][2][4];
        LOADFRAG(0, a[0], bw[0]);

        #pragma unroll
        for (int ks = 0; ks < 4; ++ks) {
            const int cur = ks & 1;
            if (ks < 3) LOADFRAG(ks + 1, a[cur ^ 1], bw[cur ^ 1]);
            #pragma unroll
            for (int mi = 0; mi < 4; ++mi)
                #pragma unroll
                for (int nj = 0; nj < 4; ++nj)
                    mma16816(acc[mi][nj], a[cur][mi],
                             bw[cur][nj >> 1][(nj & 1)*2], bw[cur][nj >> 1][(nj & 1)*2 + 1]);
        }
        if (++buf == 3) buf = 0;
    }

    // ---- epilogue ----
    float* zout; size_t ldz; int colbase;
    const float* bias = nullptr;
    if (group < 5) {
        zout = g_Z;  ldz = 5*Hd; colbase = group*Hd + n0;
        if      (group == 0) bias = bi;
        else if (group == 1) bias = bf_;
        else if (group == 2) bias = bg;
        else if (group == 3) bias = bo;
    } else {
        zout = g_Z2; ldz = 2*Hd; colbase = (group - 5)*Hd + n0;
    }

    const int gid = lane >> 2;
    const int tig = lane & 3;

    #pragma unroll
    for (int mi = 0; mi < 4; ++mi) {
        const int row = m0 + wm*64 + mi*16 + gid;
        #pragma unroll
        for (int nj = 0; nj < 4; ++nj) {
            const int ncol = wn*32 + nj*8 + tig*2;
            float b0 = 0.f, b1 = 0.f;
            if (bias) { b0 = bias[n0 + ncol]; b1 = bias[n0 + ncol + 1]; }
            float2 v0 = make_float2(acc[mi][nj][0] + b0, acc[mi][nj][1] + b1);
            float2 v1 = make_float2(acc[mi][nj][2] + b0, acc[mi][nj][3] + b1);
            *(float2*)(zout + (size_t)row       * ldz + colbase + ncol) = v0;
            *(float2*)(zout + (size_t)(row + 8) * ldz + colbase + ncol) = v1;
        }
    }
}

// ---------------- merged conversion kernel ----------------
struct WPtrs { const float* p[13]; };

// z < 13: W[K][N] fp32 -> g_Wt[N][K] fp16 (64x64 tile transpose)
// z >= 13: activation plane (z-13): fp32 -> fp16
__global__ void __launch_bounds__(256) conv_all(
    WPtrs wp,
    const float* __restrict__ x, const float* __restrict__ h, const float* __restrict__ c)
{
    const int z = blockIdx.z;
    const int tid = threadIdx.x;

    if (z < 13) {
        __shared__ float t[64][65];
        const float* w = wp.p[z];
        const int k0 = blockIdx.x * 64;
        const int n0 = blockIdx.y * 64;

        #pragma unroll
        for (int i = 0; i < 4; ++i) {
            const int idx = tid + i*256;
            const int r  = idx >> 4;
            const int c4 = idx & 15;
            float4 v = *(const float4*)(w + (size_t)(k0 + r)*Hd + n0 + c4*4);
            t[r][c4*4+0] = v.x; t[r][c4*4+1] = v.y;
            t[r][c4*4+2] = v.z; t[r][c4*4+3] = v.w;
        }
        __syncthreads();

        __half* dst = g_Wt + (size_t)z*WP;
        #pragma unroll
        for (int i = 0; i < 2; ++i) {
            const int idx = tid + i*256;
            const int n  = idx >> 3;
            const int kc = idx & 7;
            uint32_t pk[4];
            #pragma unroll
            for (int j = 0; j < 4; ++j) {
                __half h0 = __float2half_rn(t[kc*8 + 2*j    ][n]);
                __half h1 = __float2half_rn(t[kc*8 + 2*j + 1][n]);
                __half2 hh = __halves2half2(h0, h1);
                pk[j] = *(uint32_t*)&hh;
            }
            *(uint4*)(dst + (size_t)(n0 + n)*Kd + k0 + kc*8) =
                make_uint4(pk[0], pk[1], pk[2], pk[3]);
        }
    } else {
        const int act = z - 13;
        const float* s = (act == 0) ? x : (act == 1) ? h : c;
        __half* dst = g_Act + (size_t)act*AP;
        const int bid = (int)(blockIdx.y * gridDim.x + blockIdx.x);   // 0..1023
        size_t i = ((size_t)bid*256 + tid) * 4;
        #pragma unroll
        for (int it = 0; it < 8; ++it) {
            float4 v = *(const float4*)(s + i);
            __half2 h0 = __halves2half2(__float2half_rn(v.x), __float2half_rn(v.y));
            __half2 h1 = __halves2half2(__float2half_rn(v.z), __float2half_rn(v.w));
            *(uint2*)(dst + i) = make_uint2(*(uint32_t*)&h0, *(uint32_t*)&h1);
            i += (size_t)1024*256*4;
        }
    }
}

// ---------------- elementwise kernels (float4 vectorized) ----------------
__global__ void __launch_bounds__(256) cell_kernel(
    const float* __restrict__ c_prev, float* __restrict__ c_out)
{
    const int idx = (blockIdx.x * 256 + threadIdx.x) * 4;   // 4-aligned within a row
    const int m = idx >> 11;
    const int j = idx & (Hd - 1);
    const float* zr = g_Z + (size_t)m * (5*Hd);
    float4 iv = *(const float4*)(zr + j);
    float4 fv = *(const float4*)(zr + Hd + j);
    float4 gv = *(const float4*)(zr + 2*Hd + j);
    float4 cp = *(const float4*)(c_prev + idx);
    float cn[4], tc[4];
    const float* ivp = (const float*)&iv;
    const float* fvp = (const float*)&fv;
    const float* gvp = (const float*)&gv;
    const float* cpp = (const float*)&cp;
    #pragma unroll
    for (int r = 0; r < 4; ++r) {
        const float si = 1.0f / (1.0f + expf(-ivp[r]));
        const float sf = 1.0f / (1.0f + expf(-fvp[r]));
        cn[r] = sf * cpp[r] + si * tanhf(gvp[r]);
        tc[r] = tanhf(cn[r]);
    }
    *(float4*)(c_out + idx) = make_float4(cn[0], cn[1], cn[2], cn[3]);
    __half2 c0 = __halves2half2(__float2half_rn(cn[0]), __float2half_rn(cn[1]));
    __half2 c1 = __halves2half2(__float2half_rn(cn[2]), __float2half_rn(cn[3]));
    __half2 t0 = __halves2half2(__float2half_rn(tc[0]), __float2half_rn(tc[1]));
    __half2 t1 = __halves2half2(__float2half_rn(tc[2]), __float2half_rn(tc[3]));
    *(uint2*)(g_Act + 3*AP + idx) = make_uint2(*(uint32_t*)&c0, *(uint32_t*)&c1);
    *(uint2*)(g_Act + 4*AP + idx) = make_uint2(*(uint32_t*)&t0, *(uint32_t*)&t1);
}

__global__ void __launch_bounds__(256) out_kernel(float* __restrict__ h_out)
{
    const int idx = (blockIdx.x * 256 + threadIdx.x) * 4;
    const int m = idx >> 11;
    const int j = idx & (Hd - 1);
    const float* zr  = g_Z  + (size_t)m * (5*Hd);
    const float* z2r = g_Z2 + (size_t)m * (2*Hd);
    float4 op = *(const float4*)(zr + 3*Hd + j);
    float4 rs = *(const float4*)(zr + 4*Hd + j);
    float4 zc = *(const float4*)(z2r + j);
    float4 zt = *(const float4*)(z2r + Hd + j);
    const float* opp = (const float*)&op;
    const float* rsp = (const float*)&rs;
    const float* zcp = (const float*)&zc;
    const float* ztp = (const float*)&zt;
    float hv[4];
    #pragma unroll
    for (int r = 0; r < 4; ++r)
        hv[r] = tanhf(opp[r] + zcp[r]) * (ztp[r] + rsp[r]);
    *(float4*)(h_out + idx) = make_float4(hv[0], hv[1], hv[2], hv[3]);
}

// ---------------- host launcher ----------------
extern "C" void kernel_launch(void* const* d_in, const int* in_sizes, int n_in,
                              void* d_out, int out_size)
{
    const float* x      = (const float*)d_in[0];
    const float* h_prev = (const float*)d_in[1];
    const float* c_prev = (const float*)d_in[2];
    const float* w_xi = (const float*)d_in[3];
    const float* w_hi = (const float*)d_in[4];
    const float* w_ci = (const float*)d_in[5];
    const float* w_xf = (const float*)d_in[6];
    const float* w_hf = (const float*)d_in[7];
    const float* w_cf = (const float*)d_in[8];
    const float* w_xg = (const float*)d_in[9];
    const float* w_hg = (const float*)d_in[10];
    const float* w_xo = (const float*)d_in[11];
    const float* w_ho = (const float*)d_in[12];
    const float* w_co = (const float*)d_in[13];
    const float* w_c  = (const float*)d_in[14];
    const float* w_i  = (const float*)d_in[15];
    const float* b_i  = (const float*)d_in[16];
    const float* b_f  = (const float*)d_in[17];
    const float* b_g  = (const float*)d_in[18];
    const float* b_o  = (const float*)d_in[19];

    float* out   = (float*)d_out;
    float* h_out = out;
    float* c_out = out + (size_t)Bsz * Hd;

    cudaFuncSetAttribute(gemm_mma, cudaFuncAttributeMaxDynamicSharedMemorySize, SMEM_BYTES);

    const int n = Bsz * Hd;

    // all conversions in one launch: z 0..12 weights, z 13..15 activations
    WPtrs wp = {{w_xi, w_hi, w_ci, w_xf, w_hf, w_cf, w_xg, w_hg, w_xo, w_ho, w_co, w_c, w_i}};
    conv_all<<<dim3(Kd/64, Hd/64, 16), 256>>>(wp, x, h_prev, c_prev);

    // gemm phase 0: groups i,f,g (everything the cell update needs)
    gemm_mma<<<dim3(Bsz/BM, 3*16), THREADS, SMEM_BYTES>>>(0, b_i, b_f, b_g, b_o);

    cell_kernel<<<n/(256*4), 256>>>(c_prev, c_out);

    // gemm phase 1: groups o, resid, co, c
    gemm_mma<<<dim3(Bsz/BM, 4*16), THREADS, SMEM_BYTES>>>(1, b_i, b_f, b_g, b_o);

    out_kernel<<<n/(256*4), 256>>>(h_out);
}